// round 1
// baseline (speedup 1.0000x reference)
#include <cuda_runtime.h>

typedef unsigned long long u64;

#define TPB 256
#define IP 2
#define PXB (TPB * 2 * IP)   // 1024 pixels per block

__device__ __forceinline__ u64 pk2(float lo, float hi) {
    u64 r; asm("mov.b64 %0, {%1, %2};" : "=l"(r) : "f"(lo), "f"(hi)); return r;
}
__device__ __forceinline__ void unpk(u64 v, float& lo, float& hi) {
    asm("mov.b64 {%0, %1}, %2;" : "=f"(lo), "=f"(hi) : "l"(v));
}
__device__ __forceinline__ u64 ffma2(u64 a, u64 b, u64 c) {
    u64 d; asm("fma.rn.f32x2 %0, %1, %2, %3;" : "=l"(d) : "l"(a), "l"(b), "l"(c)); return d;
}
__device__ __forceinline__ u64 fmul2(u64 a, u64 b) {
    u64 d; asm("mul.rn.f32x2 %0, %1, %2;" : "=l"(d) : "l"(a), "l"(b)); return d;
}
__device__ __forceinline__ u64 fadd2(u64 a, u64 b) {
    u64 d; asm("add.rn.f32x2 %0, %1, %2;" : "=l"(d) : "l"(a), "l"(b)); return d;
}
__device__ __forceinline__ float sin_ap(float x){ float r; asm("sin.approx.f32 %0, %1;" : "=f"(r) : "f"(x)); return r; }
__device__ __forceinline__ float ex2_ap(float x){ float r; asm("ex2.approx.f32 %0, %1;" : "=f"(r) : "f"(x)); return r; }
__device__ __forceinline__ float tanh_ap(float x){ float r; asm("tanh.approx.f32 %0, %1;" : "=f"(r) : "f"(x)); return r; }

__global__ __launch_bounds__(TPB) void cppn_kernel(
    const float* __restrict__ x, const float* __restrict__ y, const float* __restrict__ rr,
    const float* __restrict__ z,
    const float* __restrict__ W0, const float* __restrict__ b0,
    const float* __restrict__ Wm, const float* __restrict__ bm,
    const float* __restrict__ Wo, const float* __restrict__ bo,
    const int* __restrict__ masks_raw,
    float* __restrict__ outp, long long n)
{
    __shared__ u64 sW0[88], sB0[8], sWm[64], sBm[8], sWo[24], sBo[3], sSel[96];
    __shared__ int sFid[24];

    const int tid = threadIdx.x;

    // ---- per-block constant prep (parallel) ----
    if (tid < 88) {
        int k = tid % 11;
        float w = W0[tid] * (k < 8 ? 0.1f : 1.0f);   // fold z / Z_SCALE into W0
        sW0[tid] = pk2(w, w);
    } else if (tid < 96)  { float w = b0[tid-88];  sB0[tid-88]  = pk2(w, w); }
    else if (tid < 160)   { float w = Wm[tid-96];  sWm[tid-96]  = pk2(w, w); }
    else if (tid < 168)   { float w = bm[tid-160]; sBm[tid-160] = pk2(w, w); }
    else if (tid < 192)   { float w = Wo[tid-168]; sWo[tid-168] = pk2(w, w); }
    else if (tid < 195)   { float w = bo[tid-192]; sBo[tid-192] = pk2(w, w); }
    else if (tid == 255) {
        // Parse masks: dtype may be int32 (JAX x64 off) or int64. Detect via
        // "layer 0's 8 entries must be a permutation of 0..7".
        int v[24];
        bool ok32 = true;
        unsigned m = 0;
        #pragma unroll
        for (int i = 0; i < 24; i++) v[i] = masks_raw[i];
        #pragma unroll
        for (int i = 0; i < 8; i++) {
            if ((unsigned)v[i] > 7u) ok32 = false; else m |= 1u << v[i];
        }
        if (!ok32 || m != 0xFFu) {
            const long long* m64 = (const long long*)masks_raw;
            #pragma unroll
            for (int i = 0; i < 24; i++) v[i] = (int)m64[i];
        }
        #pragma unroll
        for (int l = 0; l < 3; l++)
            #pragma unroll
            for (int f = 0; f < 4; f++)
                #pragma unroll
                for (int i = 0; i < 2; i++)
                    sFid[l*8 + v[l*8 + f*2 + i]] = f;
    }
    __syncthreads();
    if (tid < 96) {
        int c = tid & 3;                      // function slot: sin, gaus, tanh, id
        int f = sFid[tid >> 2];               // chosen function for (l,h)
        float s = (f == c) ? (c == 1 ? 0.3989422804014327f : 1.0f) : 0.0f;
        sSel[tid] = pk2(s, s);                // INV_SQRT_2PI folded into gaus selector
    }
    __syncthreads();

    const u64 cgau  = pk2(-0.72134752044448f, -0.72134752044448f); // -0.5*log2(e)
    const u64 chalf = pk2(0.5f, 0.5f);

    const long long base = (long long)blockIdx.x * PXB;

    u64 out[IP][8];
    bool ok[IP];
    long long ppx[IP];

    { // ---- input load + first linear (W0) ----
        u64 inp[IP][11];
        #pragma unroll
        for (int ip = 0; ip < IP; ip++) {
            long long p = base + (long long)(ip * TPB + tid) * 2;
            ppx[ip] = p;
            ok[ip] = (p + 2 <= n);
            if (ok[ip]) {
                const float4* zp = (const float4*)(z + p * 8);
                float4 za0 = zp[0], za1 = zp[1], zb0 = zp[2], zb1 = zp[3];
                float2 xv = *(const float2*)(x  + p);
                float2 yv = *(const float2*)(y  + p);
                float2 rv = *(const float2*)(rr + p);
                inp[ip][0]  = pk2(za0.x, zb0.x);
                inp[ip][1]  = pk2(za0.y, zb0.y);
                inp[ip][2]  = pk2(za0.z, zb0.z);
                inp[ip][3]  = pk2(za0.w, zb0.w);
                inp[ip][4]  = pk2(za1.x, zb1.x);
                inp[ip][5]  = pk2(za1.y, zb1.y);
                inp[ip][6]  = pk2(za1.z, zb1.z);
                inp[ip][7]  = pk2(za1.w, zb1.w);
                inp[ip][8]  = pk2(xv.x, xv.y);
                inp[ip][9]  = pk2(yv.x, yv.y);
                inp[ip][10] = pk2(rv.x, rv.y);
            } else {
                #pragma unroll
                for (int k = 0; k < 11; k++) inp[ip][k] = 0ull;
            }
        }
        #pragma unroll
        for (int j = 0; j < 8; j++) {
            u64 a0 = sB0[j], a1 = sB0[j];
            #pragma unroll
            for (int k = 0; k < 11; k++) {
                u64 w = sW0[j*11 + k];
                a0 = ffma2(inp[0][k], w, a0);
                a1 = ffma2(inp[1][k], w, a1);
            }
            out[0][j] = a0; out[1][j] = a1;
        }
    }

    // ---- 3 residual layers with selected activations ----
    #pragma unroll
    for (int l = 0; l < 3; l++) {
        u64 pre[IP][8];
        #pragma unroll
        for (int j = 0; j < 8; j++) {
            u64 a0 = sBm[j], a1 = sBm[j];
            #pragma unroll
            for (int k = 0; k < 8; k++) {
                u64 w = sWm[j*8 + k];
                a0 = ffma2(out[0][k], w, a0);
                a1 = ffma2(out[1][k], w, a1);
            }
            pre[0][j] = a0; pre[1][j] = a1;
        }
        #pragma unroll
        for (int j = 0; j < 8; j++) {
            u64 s0 = sSel[(l*8 + j)*4 + 0];
            u64 s1 = sSel[(l*8 + j)*4 + 1];
            u64 s2 = sSel[(l*8 + j)*4 + 2];
            u64 s3 = sSel[(l*8 + j)*4 + 3];
            #pragma unroll
            for (int ip = 0; ip < IP; ip++) {
                u64 t = pre[ip][j];
                float ta, tb; unpk(t, ta, tb);
                u64 sn = pk2(sin_ap(ta), sin_ap(tb));
                u64 ga = fmul2(fmul2(t, t), cgau);
                float g0, g1; unpk(ga, g0, g1);
                u64 gs = pk2(ex2_ap(g0), ex2_ap(g1));
                u64 th = pk2(tanh_ap(ta), tanh_ap(tb));
                u64 v = fmul2(s0, sn);
                v = ffma2(s1, gs, v);
                v = ffma2(s2, th, v);
                v = ffma2(s3, t,  v);
                out[ip][j] = fmul2(fadd2(v, out[ip][j]), chalf);
            }
        }
    }

    // ---- output linear + sigmoid (via tanh) + store ----
    #pragma unroll
    for (int ip = 0; ip < IP; ip++) {
        if (!ok[ip]) continue;
        float res[6];
        #pragma unroll
        for (int o = 0; o < 3; o++) {
            u64 a = sBo[o];
            #pragma unroll
            for (int k = 0; k < 8; k++) a = ffma2(out[ip][k], sWo[o*8 + k], a);
            float ua, ub; unpk(a, ua, ub);
            res[o]     = fmaf(tanh_ap(0.5f * ua), 0.5f, 0.5f);
            res[3 + o] = fmaf(tanh_ap(0.5f * ub), 0.5f, 0.5f);
        }
        float2* op = (float2*)(outp + ppx[ip] * 3);
        op[0] = make_float2(res[0], res[1]);
        op[1] = make_float2(res[2], res[3]);
        op[2] = make_float2(res[4], res[5]);
    }
}

extern "C" void kernel_launch(void* const* d_in, const int* in_sizes, int n_in,
                              void* d_out, int out_size) {
    const float* x  = (const float*)d_in[0];
    const float* y  = (const float*)d_in[1];
    const float* r  = (const float*)d_in[2];
    const float* z  = (const float*)d_in[3];
    const float* W0 = (const float*)d_in[4];
    const float* b0 = (const float*)d_in[5];
    const float* Wm = (const float*)d_in[6];
    const float* bm = (const float*)d_in[7];
    const float* Wo = (const float*)d_in[8];
    const float* bo = (const float*)d_in[9];
    const int* masks = (const int*)d_in[10];

    long long n = (long long)in_sizes[0];
    int blocks = (int)((n + PXB - 1) / PXB);
    cppn_kernel<<<blocks, TPB>>>(x, y, r, z, W0, b0, Wm, bm, Wo, bo, masks,
                                 (float*)d_out, n);
}